// round 1
// baseline (speedup 1.0000x reference)
#include <cuda_runtime.h>
#include <math.h>

// ---------------- problem constants (fixed shapes) ----------------
#define B   8
#define NW  5
#define KSH 5
#define HW  196        // 14*14
#define C   512
#define DKV 128
#define S   200        // B*NW*KSH support maps
#define BN  40         // B*NW
#define KIJ 980        // KSH*HW
#define CHW (C*HW)     // 100352
#define OHW (256*HW)   // 50176
#define AHW (KIJ*HW)   // 192080
#define SCALE 0.08838834764831843f   // 128^-0.5

// ---------------- scratch (static device globals; no allocs) ----------------
__device__ float g_avg[C];
__device__ float g_bias2[64];
__device__ float g_t1[B*64*HW];
__device__ float g_wt[B*64*HW];
__device__ float g_qkv[B*256*HW];     // query projections [b][o][hw], o<128:Q, o>=128:V
__device__ float g_skv[S*256*HW];     // support projections [s][o][hw]
__device__ float g_attn[BN*KIJ*HW];   // sim/exp, layout [bn][kij][hw]  (~30.7 MB)
__device__ float g_sinv[BN*HW];       // 1/softmax-sum per (bn,hw)
__device__ float g_out[BN*DKV*HW];

// ---------------- K1: per-channel mean of supports ----------------
__global__ void k_avg(const float* __restrict__ sup) {
    int c = blockIdx.x;
    float s = 0.f;
    for (int i = threadIdx.x; i < S*HW; i += 256) {
        int ss = i / HW, hw = i - ss*HW;
        s += sup[ss*CHW + c*HW + hw];
    }
    __shared__ float red[256];
    red[threadIdx.x] = s; __syncthreads();
    for (int o = 128; o > 0; o >>= 1) {
        if (threadIdx.x < o) red[threadIdx.x] += red[threadIdx.x + o];
        __syncthreads();
    }
    if (threadIdx.x == 0) g_avg[c] = red[0] * (1.f/(S*HW));
}

// ---------------- K2: bias2[o] = w_s1[o, 512:1024] . avg ----------------
__global__ void k_bias2(const float* __restrict__ ws1) {
    __shared__ float av[C];
    for (int i = threadIdx.x; i < C; i += 64) av[i] = g_avg[i];
    __syncthreads();
    int o = threadIdx.x;
    float s = 0.f;
    for (int c = 0; c < C; c++) s = fmaf(ws1[o*1024 + 512 + c], av[c], s);
    g_bias2[o] = s;
}

// ---------------- K3: batched projection GEMM ----------------
// supports: blocks 0..799   -> C[s, 0:256, hw] = [Wqk;Wv][256,512] x X[512,196]
// queries : blocks 800..839 -> rows 0:256 as above + rows 256:320 = w_s1[:, :512]
// tile 64 rows x 196 cols, 224 threads, 8x7 micro-tile, KC=16
#define KC 16
__global__ void __launch_bounds__(224) k_proj(const float* __restrict__ sup,
                                              const float* __restrict__ qry,
                                              const float* __restrict__ wqk,
                                              const float* __restrict__ wv,
                                              const float* __restrict__ ws1) {
    __shared__ float Ws[KC][64];
    __shared__ float Xs[KC][HW];
    int idx = blockIdx.x;
    const float* X; int rowbase, b = 0, bb = 0; bool isq;
    if (idx < 800) { bb = idx >> 2; rowbase = (idx & 3) * 64; X = sup + bb*CHW; isq = false; }
    else { int j = idx - 800; b = j / 5; rowbase = (j % 5) * 64; X = qry + b*CHW; isq = true; }
    int t = threadIdx.x;
    int tr = t / 28, tc = t - tr*28;
    float acc[8][7];
    #pragma unroll
    for (int i = 0; i < 8; i++)
        #pragma unroll
        for (int j = 0; j < 7; j++) acc[i][j] = 0.f;

    for (int k0 = 0; k0 < C; k0 += KC) {
        for (int i = t; i < KC*64; i += 224) {
            int ro = i >> 4, kk = i & 15;
            int gr = rowbase + ro, cc = k0 + kk;
            float w;
            if (gr < 128)      w = wqk[gr*C + cc];
            else if (gr < 256) w = wv[(gr-128)*C + cc];
            else               w = ws1[(gr-256)*1024 + cc];
            Ws[kk][ro] = w;
        }
        #pragma unroll 2
        for (int i = t; i < KC*HW; i += 224) {
            int kk = i / HW, hw = i - kk*HW;
            Xs[kk][hw] = X[(k0+kk)*HW + hw];
        }
        __syncthreads();
        #pragma unroll
        for (int kk = 0; kk < KC; kk++) {
            float a[8], x[7];
            #pragma unroll
            for (int i = 0; i < 8; i++) a[i] = Ws[kk][tr*8 + i];
            #pragma unroll
            for (int j = 0; j < 7; j++) x[j] = Xs[kk][tc*7 + j];
            #pragma unroll
            for (int i = 0; i < 8; i++)
                #pragma unroll
                for (int j = 0; j < 7; j++) acc[i][j] = fmaf(a[i], x[j], acc[i][j]);
        }
        __syncthreads();
    }
    #pragma unroll
    for (int i = 0; i < 8; i++) {
        int gr = rowbase + tr*8 + i;
        #pragma unroll
        for (int j = 0; j < 7; j++) {
            int col = tc*7 + j;
            float v = acc[i][j];
            if (!isq)          g_skv[bb*OHW + gr*HW + col] = v;
            else if (gr < 256) g_qkv[b*OHW + gr*HW + col] = v;
            else               g_t1[b*64*HW + (gr-256)*HW + col] = v;
        }
    }
}

// ---------------- K4: score head conv2 + sigmoid ----------------
// wt[b,64,hw] = sigmoid( w_s2 @ (t1 + bias2) ), per-b [64,64]x[64,196]
__global__ void __launch_bounds__(196) k_wt(const float* __restrict__ ws2) {
    __shared__ float Ts[64][49];
    __shared__ float W2[64][65];   // padded vs bank conflicts
    int b  = blockIdx.x >> 2;
    int c0 = (blockIdx.x & 3) * 49;
    int t = threadIdx.x;
    for (int i = t; i < 64*49; i += 196) {
        int o = i / 49, cc = i - o*49;
        Ts[o][cc] = g_t1[b*64*HW + o*HW + c0 + cc] + g_bias2[o];
    }
    for (int i = t; i < 64*64; i += 196) W2[i >> 6][i & 63] = ws2[i];
    __syncthreads();
    int col = t % 49, og = t / 49;  // og in 0..3
    float acc[16];
    #pragma unroll
    for (int i = 0; i < 16; i++) acc[i] = 0.f;
    for (int kk = 0; kk < 64; kk++) {
        float tv = Ts[kk][col];
        #pragma unroll
        for (int i = 0; i < 16; i++) acc[i] = fmaf(W2[og*16 + i][kk], tv, acc[i]);
    }
    #pragma unroll
    for (int i = 0; i < 16; i++) {
        float v = 1.f / (1.f + __expf(-acc[i]));
        g_wt[b*64*HW + (og*16 + i)*HW + c0 + col] = v;
    }
}

// ---------------- K5: sim (transposed): attn[bn][kij][hw] = SCALE * K^T Q ----------------
// per (bn): rows=kij(980), cols=hw(196); tile 49x196, 196 thr, 7x7 micro, K=128
__global__ void __launch_bounds__(196) k_sim() {
    __shared__ float Ks[16][49];
    __shared__ float Qs[16][HW];
    int bn = blockIdx.x / 20;
    int rt = blockIdx.x - bn*20;
    int b  = bn / 5;
    int s  = bn*5 + (rt >> 2);
    int ij0 = (rt & 3) * 49;
    int t = threadIdx.x;
    int tr = t / 28, tc = t - tr*28;
    float acc[7][7];
    #pragma unroll
    for (int i = 0; i < 7; i++)
        #pragma unroll
        for (int j = 0; j < 7; j++) acc[i][j] = 0.f;

    for (int k0 = 0; k0 < 128; k0 += 16) {
        for (int i = t; i < 16*49; i += 196) {
            int kk = i / 49, r = i - kk*49;
            Ks[kk][r] = g_skv[s*OHW + (k0+kk)*HW + ij0 + r];
        }
        #pragma unroll 2
        for (int i = t; i < 16*HW; i += 196) {
            int kk = i / HW, hw = i - kk*HW;
            Qs[kk][hw] = g_qkv[b*OHW + (k0+kk)*HW + hw];
        }
        __syncthreads();
        #pragma unroll
        for (int kk = 0; kk < 16; kk++) {
            float a[7], x[7];
            #pragma unroll
            for (int i = 0; i < 7; i++) a[i] = Ks[kk][tr*7 + i];
            #pragma unroll
            for (int j = 0; j < 7; j++) x[j] = Qs[kk][tc*7 + j];
            #pragma unroll
            for (int i = 0; i < 7; i++)
                #pragma unroll
                for (int j = 0; j < 7; j++) acc[i][j] = fmaf(a[i], x[j], acc[i][j]);
        }
        __syncthreads();
    }
    #pragma unroll
    for (int i = 0; i < 7; i++) {
        int row = rt*49 + tr*7 + i;
        #pragma unroll
        for (int j = 0; j < 7; j++)
            g_attn[bn*AHW + row*HW + tc*7 + j] = acc[i][j] * SCALE;
    }
}

// ---------------- K6: softmax over kij (columns coalesced); writes exp, keeps 1/sum ----------------
__global__ void __launch_bounds__(196) k_softmax() {
    int bn = blockIdx.x;
    float* base = g_attn + bn*AHW + threadIdx.x;
    float m = -1e30f;
    for (int r = 0; r < KIJ; r++) m = fmaxf(m, base[r*HW]);
    float ssum = 0.f;
    for (int r = 0; r < KIJ; r++) {
        float e = __expf(base[r*HW] - m);
        ssum += e;
        base[r*HW] = e;
    }
    g_sinv[bn*HW + threadIdx.x] = 1.f / ssum;
}

// ---------------- K7: out[bn][dv][hw] = (V . exp-attn) * sinv ----------------
// per (bn): M=128(dv), N=196(hw), K=980; tile 32x196, 224 thr, 4x7 micro, KC=28
#define KCO 28
__global__ void __launch_bounds__(224) k_out() {
    __shared__ float Vs[KCO][32];
    __shared__ float As[KCO][HW];
    int bn = blockIdx.x >> 2;
    int rt = blockIdx.x & 3;
    int t = threadIdx.x;
    int tr = t / 28, tc = t - tr*28;
    float acc[4][7];
    #pragma unroll
    for (int i = 0; i < 4; i++)
        #pragma unroll
        for (int j = 0; j < 7; j++) acc[i][j] = 0.f;

    for (int k0 = 0; k0 < KIJ; k0 += KCO) {
        int k   = k0 / HW;          // 196 % 28 == 0 -> chunk never crosses a k boundary
        int ij0 = k0 - k*HW;
        const float* vbase = g_skv + (bn*5 + k)*OHW + (128 + rt*32)*HW + ij0;
        for (int i = t; i < KCO*32; i += 224) {
            int r = i / 28, kk = i - r*28;     // kk fastest -> coalesced
            Vs[kk][r] = vbase[r*HW + kk];
        }
        #pragma unroll 2
        for (int i = t; i < KCO*HW; i += 224) {
            int kk = i / HW, hw = i - kk*HW;
            As[kk][hw] = g_attn[bn*AHW + (k0+kk)*HW + hw];
        }
        __syncthreads();
        #pragma unroll
        for (int kk = 0; kk < KCO; kk++) {
            float a[4], x[7];
            #pragma unroll
            for (int i = 0; i < 4; i++) a[i] = Vs[kk][tr*4 + i];
            #pragma unroll
            for (int j = 0; j < 7; j++) x[j] = As[kk][tc*7 + j];
            #pragma unroll
            for (int i = 0; i < 4; i++)
                #pragma unroll
                for (int j = 0; j < 7; j++) acc[i][j] = fmaf(a[i], x[j], acc[i][j]);
        }
        __syncthreads();
    }
    #pragma unroll
    for (int j = 0; j < 7; j++) {
        int col = tc*7 + j;
        float inv = g_sinv[bn*HW + col];
        #pragma unroll
        for (int i = 0; i < 4; i++)
            g_out[bn*DKV*HW + (rt*32 + tr*4 + i)*HW + col] = acc[i][j] * inv;
    }
}

// ---------------- K8: weighted L2 score ----------------
__global__ void k_score(float* __restrict__ out) {
    int bn = blockIdx.x;
    int b = bn / 5;
    float ss = 0.f;
    for (int i = threadIdx.x; i < DKV*HW; i += 256) {
        int dv = i / HW, hw = i - dv*HW;
        float w = g_wt[b*64*HW + (dv & 63)*HW + hw];
        float d = g_qkv[b*OHW + (128 + dv)*HW + hw] - g_out[bn*DKV*HW + i];
        ss = fmaf(w, d*d, ss);
    }
    __shared__ float red[256];
    red[threadIdx.x] = ss; __syncthreads();
    for (int o = 128; o > 0; o >>= 1) {
        if (threadIdx.x < o) red[threadIdx.x] += red[threadIdx.x + o];
        __syncthreads();
    }
    if (threadIdx.x == 0) out[bn] = -red[0] * (1.f/HW);
}

// ---------------- launch ----------------
extern "C" void kernel_launch(void* const* d_in, const int* in_sizes, int n_in,
                              void* d_out, int out_size) {
    const float* qry = (const float*)d_in[0];
    const float* sup = (const float*)d_in[1];
    const float* wqk = (const float*)d_in[2];
    const float* wv  = (const float*)d_in[3];
    const float* ws1 = (const float*)d_in[4];
    const float* ws2 = (const float*)d_in[5];
    float* out = (float*)d_out;

    k_avg<<<C, 256>>>(sup);
    k_proj<<<840, 224>>>(sup, qry, wqk, wv, ws1);
    k_bias2<<<1, 64>>>(ws1);
    k_wt<<<32, 196>>>(ws2);
    k_sim<<<800, 196>>>();
    k_softmax<<<BN, 196>>>();
    k_out<<<160, 224>>>();
    k_score<<<BN, 256>>>(out);
}

// round 4
// speedup vs baseline: 1.2174x; 1.2174x over previous
#include <cuda_runtime.h>
#include <math.h>

// ---------------- problem constants (fixed shapes) ----------------
#define B   8
#define NW  5
#define KSH 5
#define HW  196        // 14*14
#define C   512
#define DKV 128
#define S   200        // B*NW*KSH support maps
#define BN  40         // B*NW
#define KIJ 980        // KSH*HW
#define CHW (C*HW)     // 100352
#define OHW (256*HW)   // 50176
#define SCALE 0.08838834764831843f   // 128^-0.5

// ---------------- scratch (static device globals; no allocs) ----------------
__device__ float g_avg[C];
__device__ float g_bias2[64];
__device__ float g_t1[B*64*HW];
__device__ float g_wt[B*64*HW];
__device__ float g_qkv[B*256*HW];     // query projections [b][o][hw], o<128:Q, o>=128:V
__device__ float g_skv[S*256*HW];     // support projections [s][o][hw]
__device__ float g_part[BN*4];        // per (bn, col-tile) score partials

// ---------------- K1: per-channel mean of supports ----------------
__global__ void k_avg(const float* __restrict__ sup) {
    int c = blockIdx.x;
    float s = 0.f;
    for (int i = threadIdx.x; i < S*HW; i += 256) {
        int ss = i / HW, hw = i - ss*HW;
        s += sup[ss*CHW + c*HW + hw];
    }
    __shared__ float red[256];
    red[threadIdx.x] = s; __syncthreads();
    for (int o = 128; o > 0; o >>= 1) {
        if (threadIdx.x < o) red[threadIdx.x] += red[threadIdx.x + o];
        __syncthreads();
    }
    if (threadIdx.x == 0) g_avg[c] = red[0] * (1.f/(S*HW));
}

// ---------------- K2: bias2[o] = w_s1[o, 512:1024] . avg ----------------
__global__ void k_bias2(const float* __restrict__ ws1) {
    __shared__ float av[C];
    for (int i = threadIdx.x; i < C; i += 64) av[i] = g_avg[i];
    __syncthreads();
    int o = threadIdx.x;
    float s = 0.f;
    for (int c = 0; c < C; c++) s = fmaf(ws1[o*1024 + 512 + c], av[c], s);
    g_bias2[o] = s;
}

// ---------------- K3: batched projection GEMM ----------------
// supports: blocks 0..799   -> C[s, 0:256, hw] = [Wqk;Wv][256,512] x X[512,196]
// queries : blocks 800..839 -> rows 0:256 as above + rows 256:320 = w_s1[:, :512]
#define KC 16
__global__ void __launch_bounds__(224) k_proj(const float* __restrict__ sup,
                                              const float* __restrict__ qry,
                                              const float* __restrict__ wqk,
                                              const float* __restrict__ wv,
                                              const float* __restrict__ ws1) {
    __shared__ float Ws[KC][64];
    __shared__ float Xs[KC][HW];
    int idx = blockIdx.x;
    const float* X; int rowbase, b = 0, bb = 0; bool isq;
    if (idx < 800) { bb = idx >> 2; rowbase = (idx & 3) * 64; X = sup + bb*CHW; isq = false; }
    else { int j = idx - 800; b = j / 5; rowbase = (j % 5) * 64; X = qry + b*CHW; isq = true; }
    int t = threadIdx.x;
    int tr = t / 28, tc = t - tr*28;
    float acc[8][7];
    #pragma unroll
    for (int i = 0; i < 8; i++)
        #pragma unroll
        for (int j = 0; j < 7; j++) acc[i][j] = 0.f;

    for (int k0 = 0; k0 < C; k0 += KC) {
        for (int i = t; i < KC*64; i += 224) {
            int ro = i >> 4, kk = i & 15;
            int gr = rowbase + ro, cc = k0 + kk;
            float w;
            if (gr < 128)      w = wqk[gr*C + cc];
            else if (gr < 256) w = wv[(gr-128)*C + cc];
            else               w = ws1[(gr-256)*1024 + cc];
            Ws[kk][ro] = w;
        }
        // X rows are 196 floats = 49 float4, rows 16B-aligned (196*4=784 % 16 == 0)
        for (int i = t; i < KC*49; i += 224) {
            int kk = i / 49, q = i - kk*49;
            ((float4*)Xs[kk])[q] = ((const float4*)(X + (k0+kk)*HW))[q];
        }
        __syncthreads();
        #pragma unroll
        for (int kk = 0; kk < KC; kk++) {
            float a[8], x[7];
            #pragma unroll
            for (int i = 0; i < 8; i++) a[i] = Ws[kk][tr*8 + i];
            #pragma unroll
            for (int j = 0; j < 7; j++) x[j] = Xs[kk][tc*7 + j];
            #pragma unroll
            for (int i = 0; i < 8; i++)
                #pragma unroll
                for (int j = 0; j < 7; j++) acc[i][j] = fmaf(a[i], x[j], acc[i][j]);
        }
        __syncthreads();
    }
    #pragma unroll
    for (int i = 0; i < 8; i++) {
        int gr = rowbase + tr*8 + i;
        #pragma unroll
        for (int j = 0; j < 7; j++) {
            int col = tc*7 + j;
            float v = acc[i][j];
            if (!isq)          g_skv[bb*OHW + gr*HW + col] = v;
            else if (gr < 256) g_qkv[b*OHW + gr*HW + col] = v;
            else               g_t1[b*64*HW + (gr-256)*HW + col] = v;
        }
    }
}

// ---------------- K4: score head conv2 + sigmoid ----------------
__global__ void __launch_bounds__(196) k_wt(const float* __restrict__ ws2) {
    __shared__ float Ts[64][49];
    __shared__ float W2[64][65];
    int b  = blockIdx.x >> 2;
    int c0 = (blockIdx.x & 3) * 49;
    int t = threadIdx.x;
    for (int i = t; i < 64*49; i += 196) {
        int o = i / 49, cc = i - o*49;
        Ts[o][cc] = g_t1[b*64*HW + o*HW + c0 + cc] + g_bias2[o];
    }
    for (int i = t; i < 64*64; i += 196) W2[i >> 6][i & 63] = ws2[i];
    __syncthreads();
    int col = t % 49, og = t / 49;
    float acc[16];
    #pragma unroll
    for (int i = 0; i < 16; i++) acc[i] = 0.f;
    for (int kk = 0; kk < 64; kk++) {
        float tv = Ts[kk][col];
        #pragma unroll
        for (int i = 0; i < 16; i++) acc[i] = fmaf(W2[og*16 + i][kk], tv, acc[i]);
    }
    #pragma unroll
    for (int i = 0; i < 16; i++) {
        float v = 1.f / (1.f + __expf(-acc[i]));
        g_wt[b*64*HW + (og*16 + i)*HW + c0 + col] = v;
    }
}

// ---------------- K5: fused attention (sim + exp-softmax(no max) + out + score) ----------------
// grid = BN*4 (bn x 49-col tile, padded to 56 cols). 224 threads.
// DYNAMIC smem (~66 KB > 48 KB static limit). Struct overlay on extern shared.
#define CP 132
struct AttSmem {
    float Qt[56][CP];   // [col][c]
    float Kr[28][CP];   // [r][c]
    float Vs[128][28];  // [dv][r]
    float Et[56][28];   // [col][r]
    float Sred[4][56];
    float Rr[7];
};

__global__ void __launch_bounds__(224) k_att() {
    extern __shared__ char smem_raw[];
    AttSmem* sm = (AttSmem*)smem_raw;

    int bn = blockIdx.x >> 2, colt = blockIdx.x & 3;
    int b = bn / 5;
    int q0 = colt * 49;
    int t = threadIdx.x;

    // load Q tile transposed (clamp padded cols to 48)
    for (int i = t; i < 128*56; i += 224) {
        int c = i / 56, cp = i - c*56;
        int col = cp < 49 ? cp : 48;
        sm->Qt[cp][c] = g_qkv[b*OHW + c*HW + q0 + col];
    }

    int sg = t / 56, scp = t - sg*56;    // sim mapping: 7 rows x 1 col
    int r0 = sg * 7;
    int dg = t / 28, cp2 = t - dg*28;    // out mapping: 16 dv x 2 cols
    int dvb = dg * 16, c20 = cp2 * 2;

    float accv[16][2];
    #pragma unroll
    for (int i = 0; i < 16; i++) { accv[i][0] = 0.f; accv[i][1] = 0.f; }
    float ssum = 0.f;

    __syncthreads();

    for (int ch = 0; ch < 35; ch++) {
        int k = ch / 7, ij0 = (ch - k*7) * 28;
        const float* kb = g_skv + (bn*5 + k)*OHW + ij0;
        // load K chunk transposed + V chunk (coalesced: r fastest)
        for (int i = t; i < 128*28; i += 224) {
            int c = i / 28, r = i - c*28;
            sm->Kr[r][c] = kb[c*HW + r];
        }
        for (int i = t; i < 128*28; i += 224) {
            int dv = i / 28, r = i - dv*28;
            sm->Vs[dv][r] = kb[(128 + dv)*HW + r];
        }
        __syncthreads();

        // sim: 7 rows x 1 col per thread
        float sa[7];
        #pragma unroll
        for (int i = 0; i < 7; i++) sa[i] = 0.f;
        #pragma unroll 4
        for (int c4 = 0; c4 < 128; c4 += 4) {
            float4 q = *(const float4*)&sm->Qt[scp][c4];
            #pragma unroll
            for (int i = 0; i < 7; i++) {
                float4 kv = *(const float4*)&sm->Kr[r0 + i][c4];
                sa[i] = fmaf(kv.x, q.x, fmaf(kv.y, q.y, fmaf(kv.z, q.z, fmaf(kv.w, q.w, sa[i]))));
            }
        }
        #pragma unroll
        for (int i = 0; i < 7; i++) {
            float e = __expf(sa[i] * SCALE);
            sm->Et[scp][r0 + i] = e;
            ssum += e;
        }
        __syncthreads();

        // out: acc[dv][col] += V . E, 16 dv x 2 cols per thread, float4 over r
        #pragma unroll
        for (int r4 = 0; r4 < 28; r4 += 4) {
            float4 e0 = *(const float4*)&sm->Et[c20][r4];
            float4 e1 = *(const float4*)&sm->Et[c20 + 1][r4];
            #pragma unroll
            for (int i = 0; i < 16; i++) {
                float4 v = *(const float4*)&sm->Vs[dvb + i][r4];
                accv[i][0] = fmaf(v.x, e0.x, fmaf(v.y, e0.y, fmaf(v.z, e0.z, fmaf(v.w, e0.w, accv[i][0]))));
                accv[i][1] = fmaf(v.x, e1.x, fmaf(v.y, e1.y, fmaf(v.z, e1.z, fmaf(v.w, e1.w, accv[i][1]))));
            }
        }
        __syncthreads();
    }

    // reduce softmax column sums over the 4 sg groups
    sm->Sred[sg][scp] = ssum;
    __syncthreads();

    // epilogue: normalize + weighted L2 partial
    float ss = 0.f;
    #pragma unroll
    for (int cc = 0; cc < 2; cc++) {
        int col = c20 + cc;
        if (col < 49) {
            float inv = 1.f / (sm->Sred[0][col] + sm->Sred[1][col] + sm->Sred[2][col] + sm->Sred[3][col]);
            int hw = q0 + col;
            #pragma unroll
            for (int i = 0; i < 16; i++) {
                int dv = dvb + i;
                float o = accv[i][cc] * inv;
                float w = g_wt[b*64*HW + (dv & 63)*HW + hw];
                float qv = g_qkv[b*OHW + (128 + dv)*HW + hw];
                float d = qv - o;
                ss = fmaf(w, d*d, ss);
            }
        }
    }
    // block reduce ss
    #pragma unroll
    for (int o = 16; o > 0; o >>= 1) ss += __shfl_down_sync(0xFFFFFFFF, ss, o);
    if ((t & 31) == 0) sm->Rr[t >> 5] = ss;
    __syncthreads();
    if (t == 0) {
        float tot = 0.f;
        #pragma unroll
        for (int i = 0; i < 7; i++) tot += sm->Rr[i];
        g_part[bn*4 + colt] = tot;
    }
}

// ---------------- K6: deterministic final reduction ----------------
__global__ void k_fin(float* __restrict__ out) {
    int bn = threadIdx.x;
    if (bn < BN) {
        float* p = g_part + bn*4;
        out[bn] = -(p[0] + p[1] + p[2] + p[3]) * (1.f/HW);
    }
}

// ---------------- launch ----------------
extern "C" void kernel_launch(void* const* d_in, const int* in_sizes, int n_in,
                              void* d_out, int out_size) {
    const float* qry = (const float*)d_in[0];
    const float* sup = (const float*)d_in[1];
    const float* wqk = (const float*)d_in[2];
    const float* wv  = (const float*)d_in[3];
    const float* ws1 = (const float*)d_in[4];
    const float* ws2 = (const float*)d_in[5];
    float* out = (float*)d_out;

    // host-side attribute set: not a stream op, legal under graph capture, deterministic
    cudaFuncSetAttribute(k_att, cudaFuncAttributeMaxDynamicSharedMemorySize,
                         (int)sizeof(AttSmem));

    k_avg<<<C, 256>>>(sup);
    k_proj<<<840, 224>>>(sup, qry, wqk, wv, ws1);
    k_bias2<<<1, 64>>>(ws1);
    k_wt<<<32, 196>>>(ws2);
    k_att<<<160, 224, sizeof(AttSmem)>>>();
    k_fin<<<1, 64>>>(out);
}

// round 8
// speedup vs baseline: 1.3492x; 1.1083x over previous
#include <cuda_runtime.h>
#include <cuda_bf16.h>
#include <cstdint>
#include <math.h>

// ---------------- problem constants (fixed shapes) ----------------
#define B   8
#define NW  5
#define KSH 5
#define HW  196        // 14*14
#define C   512
#define DKV 128
#define S   200        // B*NW*KSH support maps
#define BN  40         // B*NW
#define CHW (C*HW)     // 100352
#define OHW (256*HW)   // 50176
#define SCALE 0.08838834764831843f   // 128^-0.5

// ---------------- scratch (static device globals; zero-initialized) ----------------
__device__ float g_avg[C];
__device__ float g_bias2[64];
__device__ float g_t1[B*64*HW];
__device__ float g_wt[B*64*HW];
__device__ float g_qkv[B*256*HW];     // query projections [b][o][hw]
__device__ float g_skv[S*256*HW];     // support projections [s][o][hw]
__device__ float g_part[BN*4];
__device__ __nv_bfloat16 g_wh[256*C];        // W hi  (rows 0-127 wqk, 128-255 wv)
__device__ __nv_bfloat16 g_wl[256*C];        // W lo
__device__ __nv_bfloat16 g_xth[S*256*C];     // X^T hi [s][n pad 256][k]; pad rows stay 0
__device__ __nv_bfloat16 g_xtl[S*256*C];     // X^T lo

// ---------------- K0a: convert W (wqk;wv) to bf16 hi/lo ----------------
__global__ void k_cvt_w(const float* __restrict__ wqk, const float* __restrict__ wv) {
    int gr = blockIdx.x;
    const float* src = gr < 128 ? wqk + gr*C : wv + (gr-128)*C;
    for (int k = threadIdx.x; k < C; k += 128) {
        float v = src[k];
        __nv_bfloat16 h = __float2bfloat16(v);
        __nv_bfloat16 l = __float2bfloat16(v - __bfloat162float(h));
        g_wh[gr*C + k] = h;
        g_wl[gr*C + k] = l;
    }
}

// ---------------- K0b: transpose+convert supports X -> X^T bf16 hi/lo ----------------
__global__ void __launch_bounds__(256) k_cvt_x(const float* __restrict__ sup) {
    __shared__ float ts[32][33];
    int s = blockIdx.x;
    const float* X = sup + s*CHW;
    int t = threadIdx.x;
    for (int kt = 0; kt < 16; kt++) {
        for (int nt = 0; nt < 7; nt++) {
            int k0 = kt*32, n0 = nt*32;
            #pragma unroll
            for (int i = 0; i < 4; i++) {
                int idx = t + i*256, kk = idx >> 5, nn = idx & 31;
                int n = n0 + nn;
                ts[kk][nn] = (n < HW) ? X[(k0+kk)*HW + n] : 0.f;
            }
            __syncthreads();
            #pragma unroll
            for (int i = 0; i < 4; i++) {
                int idx = t + i*256, nn = idx >> 5, kk = idx & 31;
                int n = n0 + nn;
                if (n < HW) {
                    float v = ts[kk][nn];
                    __nv_bfloat16 h = __float2bfloat16(v);
                    __nv_bfloat16 l = __float2bfloat16(v - __bfloat162float(h));
                    g_xth[(s*256 + n)*C + k0 + kk] = h;
                    g_xtl[(s*256 + n)*C + k0 + kk] = l;
                }
            }
            __syncthreads();
        }
    }
}

// ---------------- K1: per-channel mean of supports ----------------
__global__ void k_avg(const float* __restrict__ sup) {
    int c = blockIdx.x;
    float s = 0.f;
    for (int i = threadIdx.x; i < S*HW; i += 256) {
        int ss = i / HW, hw = i - ss*HW;
        s += sup[ss*CHW + c*HW + hw];
    }
    __shared__ float red[256];
    red[threadIdx.x] = s; __syncthreads();
    for (int o = 128; o > 0; o >>= 1) {
        if (threadIdx.x < o) red[threadIdx.x] += red[threadIdx.x + o];
        __syncthreads();
    }
    if (threadIdx.x == 0) g_avg[c] = red[0] * (1.f/(S*HW));
}

// ---------------- K2: bias2[o] = w_s1[o, 512:1024] . avg ----------------
__global__ void k_bias2(const float* __restrict__ ws1) {
    __shared__ float av[C];
    for (int i = threadIdx.x; i < C; i += 64) av[i] = g_avg[i];
    __syncthreads();
    int o = threadIdx.x;
    float s = 0.f;
    for (int c = 0; c < C; c++) s = fmaf(ws1[o*1024 + 512 + c], av[c], s);
    g_bias2[o] = s;
}

// ---------------- K3a: support projection via mma.sync bf16 split (3-pass) ----------------
// grid 800 = s(200) x mt(2) x nt(2). D[128,128] = W[mt] x X^T[nt]^T, K=512.
// 8 warps as 4(m) x 2(n): warp tile 32x64. Smem [128][20 u32] (80B stride:
// STS.128-aligned, LDS banks 20g+tig mod 32 conflict-free).
__global__ void __launch_bounds__(256) k_mma(int dummy) {
    __shared__ __align__(16) uint32_t As[2][128][20];
    __shared__ __align__(16) uint32_t Bs[2][128][20];
    int t = threadIdx.x;
    int wid = t >> 5, lane = t & 31;
    int g = lane >> 2, tig = lane & 3;
    int s  = blockIdx.x >> 2;
    int mt = (blockIdx.x >> 1) & 1;
    int nt = blockIdx.x & 1;
    int wm = wid >> 1, wn = wid & 1;
    int m0 = wm*32, n0 = wn*64;

    const __nv_bfloat16* ah = g_wh + (mt*128)*C;
    const __nv_bfloat16* al = g_wl + (mt*128)*C;
    const __nv_bfloat16* bh = g_xth + (s*256 + nt*128)*C;
    const __nv_bfloat16* bl = g_xtl + (s*256 + nt*128)*C;

    float d[2][8][4];
    #pragma unroll
    for (int i = 0; i < 2; i++)
        #pragma unroll
        for (int j = 0; j < 8; j++)
            #pragma unroll
            for (int q = 0; q < 4; q++) d[i][j][q] = 0.f;

    for (int ch = 0; ch < 16; ch++) {
        #pragma unroll
        for (int i = 0; i < 2; i++) {
            int idx = t + i*256;
            int row = idx >> 2, q = idx & 3;
            *(uint4*)&As[0][row][q*4] = ((const uint4*)(ah + row*C + ch*32))[q];
            *(uint4*)&As[1][row][q*4] = ((const uint4*)(al + row*C + ch*32))[q];
            *(uint4*)&Bs[0][row][q*4] = ((const uint4*)(bh + row*C + ch*32))[q];
            *(uint4*)&Bs[1][row][q*4] = ((const uint4*)(bl + row*C + ch*32))[q];
        }
        __syncthreads();

        #pragma unroll
        for (int combo = 0; combo < 3; combo++) {
            int AH = (combo == 2) ? 1 : 0;   // (h,h),(h,l),(l,h)
            int BH = (combo == 1) ? 1 : 0;
            #pragma unroll
            for (int ks = 0; ks < 2; ks++) {
                int kb = ks*8;               // u32 col offset (k0/2)
                uint32_t a[2][4];
                #pragma unroll
                for (int m2 = 0; m2 < 2; m2++) {
                    int r = m0 + m2*16 + g;
                    a[m2][0] = As[AH][r][kb + tig];
                    a[m2][1] = As[AH][r + 8][kb + tig];
                    a[m2][2] = As[AH][r][kb + tig + 4];
                    a[m2][3] = As[AH][r + 8][kb + tig + 4];
                }
                #pragma unroll
                for (int n8 = 0; n8 < 8; n8++) {
                    int nr = n0 + n8*8 + g;
                    uint32_t b0 = Bs[BH][nr][kb + tig];
                    uint32_t b1 = Bs[BH][nr][kb + tig + 4];
                    #pragma unroll
                    for (int m2 = 0; m2 < 2; m2++) {
                        asm volatile(
                            "mma.sync.aligned.m16n8k16.row.col.f32.bf16.bf16.f32 "
                            "{%0,%1,%2,%3}, {%4,%5,%6,%7}, {%8,%9}, {%0,%1,%2,%3};"
                            : "+f"(d[m2][n8][0]), "+f"(d[m2][n8][1]),
                              "+f"(d[m2][n8][2]), "+f"(d[m2][n8][3])
                            : "r"(a[m2][0]), "r"(a[m2][1]), "r"(a[m2][2]), "r"(a[m2][3]),
                              "r"(b0), "r"(b1));
                    }
                }
            }
        }
        __syncthreads();
    }

    // epilogue: d[m2][n8] -> g_skv[s][o][hw], masked to valid hw (<196)
    float* dst = g_skv + s*OHW;
    int nbase = nt*128 + n0;
    #pragma unroll
    for (int m2 = 0; m2 < 2; m2++) {
        int o = mt*128 + m0 + m2*16 + g;
        #pragma unroll
        for (int n8 = 0; n8 < 8; n8++) {
            int nglob = nbase + n8*8 + 2*tig;
            if (nglob < HW) {
                *(float2*)(dst + o*HW + nglob)     = make_float2(d[m2][n8][0], d[m2][n8][1]);
                *(float2*)(dst + (o+8)*HW + nglob) = make_float2(d[m2][n8][2], d[m2][n8][3]);
            }
        }
    }
}

// ---------------- K3b: SIMT query projection (320 rows incl. w_s1), col-split 4 ----------------
#define KC 16
__global__ void __launch_bounds__(224) k_projq(const float* __restrict__ qry,
                                               const float* __restrict__ wqk,
                                               const float* __restrict__ wv,
                                               const float* __restrict__ ws1) {
    __shared__ float Ws[KC][64];
    __shared__ float Xs[KC][52];
    int blk = blockIdx.x;
    int b = blk / 20, rowblk = (blk / 4) % 5, colq = blk & 3;
    int rowbase = rowblk * 64, c0 = colq * 49;
    const float* X = qry + b*CHW;
    int t = threadIdx.x;
    int tr = t / 7, tc = t - tr*7;          // 32 x 7, micro 2x7
    float acc[2][7];
    #pragma unroll
    for (int i = 0; i < 2; i++)
        #pragma unroll
        for (int j = 0; j < 7; j++) acc[i][j] = 0.f;

    for (int k0 = 0; k0 < C; k0 += KC) {
        for (int i = t; i < KC*64; i += 224) {
            int ro = i >> 4, kk = i & 15;
            int gr = rowbase + ro, cc = k0 + kk;
            float w;
            if (gr < 128)      w = wqk[gr*C + cc];
            else if (gr < 256) w = wv[(gr-128)*C + cc];
            else               w = ws1[(gr-256)*1024 + cc];
            Ws[kk][ro] = w;
        }
        for (int i = t; i < KC*49; i += 224) {
            int kk = i / 49, col = i - kk*49;
            Xs[kk][col] = X[(k0+kk)*HW + c0 + col];
        }
        __syncthreads();
        #pragma unroll
        for (int kk = 0; kk < KC; kk++) {
            float a0 = Ws[kk][tr*2], a1 = Ws[kk][tr*2+1];
            #pragma unroll
            for (int j = 0; j < 7; j++) {
                float x = Xs[kk][tc*7 + j];
                acc[0][j] = fmaf(a0, x, acc[0][j]);
                acc[1][j] = fmaf(a1, x, acc[1][j]);
            }
        }
        __syncthreads();
    }
    #pragma unroll
    for (int i = 0; i < 2; i++) {
        int gr = rowbase + tr*2 + i;
        #pragma unroll
        for (int j = 0; j < 7; j++) {
            int col = c0 + tc*7 + j;
            float v = acc[i][j];
            if (gr < 256) g_qkv[b*OHW + gr*HW + col] = v;
            else          g_t1[b*64*HW + (gr-256)*HW + col] = v;
        }
    }
}

// ---------------- K4: score head conv2 + sigmoid ----------------
__global__ void __launch_bounds__(196) k_wt(const float* __restrict__ ws2) {
    __shared__ float Ts[64][49];
    __shared__ float W2[64][65];
    int b  = blockIdx.x >> 2;
    int c0 = (blockIdx.x & 3) * 49;
    int t = threadIdx.x;
    for (int i = t; i < 64*49; i += 196) {
        int o = i / 49, cc = i - o*49;
        Ts[o][cc] = g_t1[b*64*HW + o*HW + c0 + cc] + g_bias2[o];
    }
    for (int i = t; i < 64*64; i += 196) W2[i >> 6][i & 63] = ws2[i];
    __syncthreads();
    int col = t % 49, og = t / 49;
    float acc[16];
    #pragma unroll
    for (int i = 0; i < 16; i++) acc[i] = 0.f;
    for (int kk = 0; kk < 64; kk++) {
        float tv = Ts[kk][col];
        #pragma unroll
        for (int i = 0; i < 16; i++) acc[i] = fmaf(W2[og*16 + i][kk], tv, acc[i]);
    }
    #pragma unroll
    for (int i = 0; i < 16; i++) {
        float v = 1.f / (1.f + __expf(-acc[i]));
        g_wt[b*64*HW + (og*16 + i)*HW + c0 + col] = v;
    }
}

// ---------------- K5: fused attention (sim + exp + out + score) ----------------
#define CP 132
struct AttSmem {
    float Qt[56][CP];
    float Kr[28][CP];
    float Vs[128][28];
    float Et[56][28];
    float Sred[4][56];
    float Rr[7];
};

__global__ void __launch_bounds__(224) k_att() {
    extern __shared__ char smem_raw[];
    AttSmem* sm = (AttSmem*)smem_raw;

    int bn = blockIdx.x >> 2, colt = blockIdx.x & 3;
    int b = bn / 5;
    int q0 = colt * 49;
    int t = threadIdx.x;

    for (int i = t; i < 128*56; i += 224) {
        int c = i / 56, cp = i - c*56;
        int col = cp < 49 ? cp : 48;
        sm->Qt[cp][c] = g_qkv[b*OHW + c*HW + q0 + col];
    }

    int sg = t / 56, scp = t - sg*56;
    int r0 = sg * 7;
    int dg = t / 28, cp2 = t - dg*28;
    int dvb = dg * 16, c20 = cp2 * 2;

    float accv[16][2];
    #pragma unroll
    for (int i = 0; i < 16; i++) { accv[i][0] = 0.f; accv[i][1] = 0.f; }
    float ssum = 0.f;

    __syncthreads();

    for (int ch = 0; ch < 35; ch++) {
        int k = ch / 7, ij0 = (ch - k*7) * 28;
        const float* kb = g_skv + (bn*5 + k)*OHW + ij0;
        for (int i = t; i < 128*28; i += 224) {
            int c = i / 28, r = i - c*28;
            sm->Kr[r][c] = kb[c*HW + r];
        }
        for (int i = t; i < 128*28; i += 224) {
            int dv = i / 28, r = i - dv*28;
            sm->Vs[dv][r] = kb[(128 + dv)*HW + r];
        }
        __syncthreads();

        float sa[7];
        #pragma unroll
        for (int i = 0; i < 7; i++) sa[i] = 0.f;
        #pragma unroll 4
        for (int c4 = 0; c4 < 128; c4 += 4) {
            float4 q = *(const float4*)&sm->Qt[scp][c4];
            #pragma unroll
            for (int i = 0; i < 7; i++) {
                float4 kv = *(const float4*)&sm->Kr[r0 + i][c4];
                sa[i] = fmaf(kv.x, q.x, fmaf(kv.y, q.y, fmaf(kv.z, q.z, fmaf(kv.w, q.w, sa[i]))));
            }
        }
        #pragma unroll
        for (int i = 0; i < 7; i++) {
            float e = __expf(sa[i] * SCALE);
            sm->Et[scp][r0 + i] = e;
            ssum += e;
        }
        __syncthreads();

        #pragma unroll
        for (int r4 = 0; r4 < 28; r4 += 4) {
            float4 e0 = *(const float4*)&sm->Et[c20][r4];
            float4 e1 = *(const float4*)&sm->Et[c20 + 1][r4];
            #pragma unroll
            for (int i = 0; i < 16; i++) {
                float4 v = *(const float4*)&sm->Vs[dvb + i][r4];
                accv[i][0] = fmaf(v.x, e0.x, fmaf(v.y, e0.y, fmaf(v.z, e0.z, fmaf(v.w, e0.w, accv[i][0]))));
                accv[i][1] = fmaf(v.x, e1.x, fmaf(v.y, e1.y, fmaf(v.z, e1.z, fmaf(v.w, e1.w, accv[i][1]))));
            }
        }
        __syncthreads();
    }

    sm->Sred[sg][scp] = ssum;
    __syncthreads();

    float ss = 0.f;
    #pragma unroll
    for (int cc = 0; cc < 2; cc++) {
        int col = c20 + cc;
        if (col < 49) {
            float inv = 1.f / (sm->Sred[0][col] + sm->Sred[1][col] + sm->Sred[2][col] + sm->Sred[3][col]);
            int hw = q0 + col;
            #pragma unroll
            for (int i = 0; i < 16; i++) {
                int dv = dvb + i;
                float o = accv[i][cc] * inv;
                float w = g_wt[b*64*HW + (dv & 63)*HW + hw];
                float qv = g_qkv[b*OHW + (128 + dv)*HW + hw];
                float d = qv - o;
                ss = fmaf(w, d*d, ss);
            }
        }
    }
    #pragma unroll
    for (int o = 16; o > 0; o >>= 1) ss += __shfl_down_sync(0xFFFFFFFF, ss, o);
    if ((t & 31) == 0) sm->Rr[t >> 5] = ss;
    __syncthreads();
    if (t == 0) {
        float tot = 0.f;
        #pragma unroll
        for (int i = 0; i < 7; i++) tot += sm->Rr[i];
        g_part[bn*4 + colt] = tot;
    }
}

// ---------------- K6: deterministic final reduction ----------------
__global__ void k_fin(float* __restrict__ out) {
    int bn = threadIdx.x;
    if (bn < BN) {
        float* p = g_part + bn*4;
        out[bn] = -(p[0] + p[1] + p[2] + p[3]) * (1.f/HW);
    }
}

// ---------------- launch ----------------
extern "C" void kernel_launch(void* const* d_in, const int* in_sizes, int n_in,
                              void* d_out, int out_size) {
    const float* qry = (const float*)d_in[0];
    const float* sup = (const float*)d_in[1];
    const float* wqk = (const float*)d_in[2];
    const float* wv  = (const float*)d_in[3];
    const float* ws1 = (const float*)d_in[4];
    const float* ws2 = (const float*)d_in[5];
    float* out = (float*)d_out;

    cudaFuncSetAttribute(k_att, cudaFuncAttributeMaxDynamicSharedMemorySize, (int)sizeof(AttSmem));

    k_cvt_w<<<256, 128>>>(wqk, wv);
    k_cvt_x<<<S, 256>>>(sup);
    k_avg<<<C, 256>>>(sup);
    k_projq<<<160, 224>>>(qry, wqk, wv, ws1);
    k_mma<<<800, 256>>>(0);
    k_bias2<<<1, 64>>>(ws1);
    k_wt<<<32, 196>>>(ws2);
    k_att<<<160, 224, sizeof(AttSmem)>>>();
    k_fin<<<1, 64>>>(out);
}

// round 9
// speedup vs baseline: 1.3570x; 1.0058x over previous
#include <cuda_runtime.h>
#include <cuda_bf16.h>
#include <cstdint>
#include <math.h>

// ---------------- problem constants (fixed shapes) ----------------
#define B   8
#define NW  5
#define KSH 5
#define HW  196        // 14*14
#define C   512
#define DKV 128
#define S   200        // B*NW*KSH support maps
#define SQ  208        // S + B query maps
#define BN  40         // B*NW
#define CHW (C*HW)     // 100352
#define OHW (256*HW)   // 50176
#define SCALE 0.08838834764831843f   // 128^-0.5

// ---------------- scratch (static device globals; zero-initialized) ----------------
__device__ float g_avg[C];
__device__ float g_bias2[64];
__device__ float g_t1[B*64*HW];
__device__ float g_wt[B*64*HW];
__device__ float g_qkv[B*256*HW];     // query projections [b][o][hw]
__device__ float g_skv[S*256*HW];     // support projections [s][o][hw]
__device__ float g_part[BN*4];
__device__ __nv_bfloat16 g_wh[256*C];        // W hi  (rows 0-127 wqk, 128-255 wv)
__device__ __nv_bfloat16 g_wl[256*C];        // W lo
__device__ __nv_bfloat16 g_xth[SQ*256*C];    // X^T hi [s][n pad 256][k]; pad rows stay 0
__device__ __nv_bfloat16 g_xtl[SQ*256*C];    // X^T lo

// ---------------- K0a: convert W (wqk;wv) to bf16 hi/lo ----------------
__global__ void k_cvt_w(const float* __restrict__ wqk, const float* __restrict__ wv) {
    int gr = blockIdx.x;
    const float* src = gr < 128 ? wqk + gr*C : wv + (gr-128)*C;
    for (int k = threadIdx.x; k < C; k += 128) {
        float v = src[k];
        __nv_bfloat16 h = __float2bfloat16(v);
        __nv_bfloat16 l = __float2bfloat16(v - __bfloat162float(h));
        g_wh[gr*C + k] = h;
        g_wl[gr*C + k] = l;
    }
}

// ---------------- K0b: transpose+convert X (sup + qry) -> X^T bf16 hi/lo ----------------
// grid = SQ*7 (map, 32-col n-tile); 256 threads; 16 smem-transpose steps over k.
__global__ void __launch_bounds__(256) k_cvt_x(const float* __restrict__ sup,
                                               const float* __restrict__ qry) {
    __shared__ float ts[32][33];
    int bx = blockIdx.x;
    int s = bx / 7, nt = bx - s*7;
    const float* X = (s < S) ? (sup + s*CHW) : (qry + (s-S)*CHW);
    int n0 = nt * 32;
    int t = threadIdx.x;
    for (int kt = 0; kt < 16; kt++) {
        int k0 = kt * 32;
        #pragma unroll
        for (int i = 0; i < 4; i++) {
            int idx = t + i*256, kk = idx >> 5, nn = idx & 31;
            int n = n0 + nn;
            ts[kk][nn] = (n < HW) ? X[(k0+kk)*HW + n] : 0.f;
        }
        __syncthreads();
        #pragma unroll
        for (int i = 0; i < 4; i++) {
            int idx = t + i*256, nn = idx >> 5, kk = idx & 31;
            int n = n0 + nn;
            if (n < HW) {
                float v = ts[kk][nn];
                __nv_bfloat16 h = __float2bfloat16(v);
                __nv_bfloat16 l = __float2bfloat16(v - __bfloat162float(h));
                g_xth[(s*256 + n)*C + k0 + kk] = h;
                g_xtl[(s*256 + n)*C + k0 + kk] = l;
            }
        }
        __syncthreads();
    }
}

// ---------------- K1: per-channel mean of supports ----------------
__global__ void k_avg(const float* __restrict__ sup) {
    int c = blockIdx.x;
    float s = 0.f;
    for (int i = threadIdx.x; i < S*HW; i += 256) {
        int ss = i / HW, hw = i - ss*HW;
        s += sup[ss*CHW + c*HW + hw];
    }
    __shared__ float red[256];
    red[threadIdx.x] = s; __syncthreads();
    for (int o = 128; o > 0; o >>= 1) {
        if (threadIdx.x < o) red[threadIdx.x] += red[threadIdx.x + o];
        __syncthreads();
    }
    if (threadIdx.x == 0) g_avg[c] = red[0] * (1.f/(S*HW));
}

// ---------------- K2: bias2[o] = w_s1[o, 512:1024] . avg ----------------
__global__ void k_bias2(const float* __restrict__ ws1) {
    __shared__ float av[C];
    for (int i = threadIdx.x; i < C; i += 64) av[i] = g_avg[i];
    __syncthreads();
    int o = threadIdx.x;
    float s = 0.f;
    for (int c = 0; c < C; c++) s = fmaf(ws1[o*1024 + 512 + c], av[c], s);
    g_bias2[o] = s;
}

// ---------------- K2b: t1[b,64,hw] = w_s1[:, :512] x query[b] (SIMT, 8 blocks) ----------------
#define KC 16
__global__ void __launch_bounds__(224) k_t1(const float* __restrict__ qry,
                                            const float* __restrict__ ws1) {
    __shared__ float Ws[KC][64];
    __shared__ float Xs[KC][HW];
    int b = blockIdx.x;
    const float* X = qry + b*CHW;
    int t = threadIdx.x;
    int tr = t / 28, tc = t - tr*28;
    float acc[8][7];
    #pragma unroll
    for (int i = 0; i < 8; i++)
        #pragma unroll
        for (int j = 0; j < 7; j++) acc[i][j] = 0.f;

    for (int k0 = 0; k0 < C; k0 += KC) {
        for (int i = t; i < KC*64; i += 224) {
            int ro = i >> 4, kk = i & 15;
            Ws[kk][ro] = ws1[ro*1024 + k0 + kk];
        }
        for (int i = t; i < KC*49; i += 224) {
            int kk = i / 49, q = i - kk*49;
            ((float4*)Xs[kk])[q] = ((const float4*)(X + (k0+kk)*HW))[q];
        }
        __syncthreads();
        #pragma unroll
        for (int kk = 0; kk < KC; kk++) {
            float a[8], x[7];
            #pragma unroll
            for (int i = 0; i < 8; i++) a[i] = Ws[kk][tr*8 + i];
            #pragma unroll
            for (int j = 0; j < 7; j++) x[j] = Xs[kk][tc*7 + j];
            #pragma unroll
            for (int i = 0; i < 8; i++)
                #pragma unroll
                for (int j = 0; j < 7; j++) acc[i][j] = fmaf(a[i], x[j], acc[i][j]);
        }
        __syncthreads();
    }
    #pragma unroll
    for (int i = 0; i < 8; i++)
        #pragma unroll
        for (int j = 0; j < 7; j++)
            g_t1[b*64*HW + (tr*8 + i)*HW + tc*7 + j] = acc[i][j];
}

// ---------------- K3: projection via mma.sync bf16 split (3-pass) ----------------
// grid 832 = s(208) x mt(2) x nt(2). D[128,128] = W[mt] x X^T[nt]^T, K=512.
// s<200 -> g_skv; s>=200 -> g_qkv (query maps). 8 warps 4(m)x2(n), warp tile 32x64.
__global__ void __launch_bounds__(256) k_mma(int dummy) {
    __shared__ __align__(16) uint32_t As[2][128][20];
    __shared__ __align__(16) uint32_t Bs[2][128][20];
    int t = threadIdx.x;
    int wid = t >> 5, lane = t & 31;
    int g = lane >> 2, tig = lane & 3;
    int s  = blockIdx.x >> 2;
    int mt = (blockIdx.x >> 1) & 1;
    int nt = blockIdx.x & 1;
    int wm = wid >> 1, wn = wid & 1;
    int m0 = wm*32, n0 = wn*64;

    const __nv_bfloat16* ah = g_wh + (mt*128)*C;
    const __nv_bfloat16* al = g_wl + (mt*128)*C;
    const __nv_bfloat16* bh = g_xth + (s*256 + nt*128)*C;
    const __nv_bfloat16* bl = g_xtl + (s*256 + nt*128)*C;

    float d[2][8][4];
    #pragma unroll
    for (int i = 0; i < 2; i++)
        #pragma unroll
        for (int j = 0; j < 8; j++)
            #pragma unroll
            for (int q = 0; q < 4; q++) d[i][j][q] = 0.f;

    for (int ch = 0; ch < 16; ch++) {
        #pragma unroll
        for (int i = 0; i < 2; i++) {
            int idx = t + i*256;
            int row = idx >> 2, q = idx & 3;
            *(uint4*)&As[0][row][q*4] = ((const uint4*)(ah + row*C + ch*32))[q];
            *(uint4*)&As[1][row][q*4] = ((const uint4*)(al + row*C + ch*32))[q];
            *(uint4*)&Bs[0][row][q*4] = ((const uint4*)(bh + row*C + ch*32))[q];
            *(uint4*)&Bs[1][row][q*4] = ((const uint4*)(bl + row*C + ch*32))[q];
        }
        __syncthreads();

        #pragma unroll
        for (int combo = 0; combo < 3; combo++) {
            int AH = (combo == 2) ? 1 : 0;   // (h,h),(h,l),(l,h)
            int BH = (combo == 1) ? 1 : 0;
            #pragma unroll
            for (int ks = 0; ks < 2; ks++) {
                int kb = ks*8;               // u32 col offset (k0/2)
                uint32_t a[2][4];
                #pragma unroll
                for (int m2 = 0; m2 < 2; m2++) {
                    int r = m0 + m2*16 + g;
                    a[m2][0] = As[AH][r][kb + tig];
                    a[m2][1] = As[AH][r + 8][kb + tig];
                    a[m2][2] = As[AH][r][kb + tig + 4];
                    a[m2][3] = As[AH][r + 8][kb + tig + 4];
                }
                #pragma unroll
                for (int n8 = 0; n8 < 8; n8++) {
                    int nr = n0 + n8*8 + g;
                    uint32_t b0 = Bs[BH][nr][kb + tig];
                    uint32_t b1 = Bs[BH][nr][kb + tig + 4];
                    #pragma unroll
                    for (int m2 = 0; m2 < 2; m2++) {
                        asm volatile(
                            "mma.sync.aligned.m16n8k16.row.col.f32.bf16.bf16.f32 "
                            "{%0,%1,%2,%3}, {%4,%5,%6,%7}, {%8,%9}, {%0,%1,%2,%3};"
                            : "+f"(d[m2][n8][0]), "+f"(d[m2][n8][1]),
                              "+f"(d[m2][n8][2]), "+f"(d[m2][n8][3])
                            : "r"(a[m2][0]), "r"(a[m2][1]), "r"(a[m2][2]), "r"(a[m2][3]),
                              "r"(b0), "r"(b1));
                    }
                }
            }
        }
        __syncthreads();
    }

    // epilogue: d[m2][n8] -> dst[o][hw], masked to valid hw (<196)
    float* dst = (s < S) ? (g_skv + s*OHW) : (g_qkv + (s-S)*OHW);
    int nbase = nt*128 + n0;
    #pragma unroll
    for (int m2 = 0; m2 < 2; m2++) {
        int o = mt*128 + m0 + m2*16 + g;
        #pragma unroll
        for (int n8 = 0; n8 < 8; n8++) {
            int nglob = nbase + n8*8 + 2*tig;
            if (nglob < HW) {
                *(float2*)(dst + o*HW + nglob)     = make_float2(d[m2][n8][0], d[m2][n8][1]);
                *(float2*)(dst + (o+8)*HW + nglob) = make_float2(d[m2][n8][2], d[m2][n8][3]);
            }
        }
    }
}

// ---------------- K4: score head conv2 + sigmoid ----------------
__global__ void __launch_bounds__(196) k_wt(const float* __restrict__ ws2) {
    __shared__ float Ts[64][49];
    __shared__ float W2[64][65];
    int b  = blockIdx.x >> 2;
    int c0 = (blockIdx.x & 3) * 49;
    int t = threadIdx.x;
    for (int i = t; i < 64*49; i += 196) {
        int o = i / 49, cc = i - o*49;
        Ts[o][cc] = g_t1[b*64*HW + o*HW + c0 + cc] + g_bias2[o];
    }
    for (int i = t; i < 64*64; i += 196) W2[i >> 6][i & 63] = ws2[i];
    __syncthreads();
    int col = t % 49, og = t / 49;
    float acc[16];
    #pragma unroll
    for (int i = 0; i < 16; i++) acc[i] = 0.f;
    for (int kk = 0; kk < 64; kk++) {
        float tv = Ts[kk][col];
        #pragma unroll
        for (int i = 0; i < 16; i++) acc[i] = fmaf(W2[og*16 + i][kk], tv, acc[i]);
    }
    #pragma unroll
    for (int i = 0; i < 16; i++) {
        float v = 1.f / (1.f + __expf(-acc[i]));
        g_wt[b*64*HW + (og*16 + i)*HW + c0 + col] = v;
    }
}

// ---------------- K5: fused attention (sim + exp + out + score) ----------------
#define CP 132
struct AttSmem {
    float Qt[56][CP];
    float Kr[28][CP];
    float Vs[128][28];
    float Et[56][28];
    float Sred[4][56];
    float Rr[7];
};

__global__ void __launch_bounds__(224) k_att() {
    extern __shared__ char smem_raw[];
    AttSmem* sm = (AttSmem*)smem_raw;

    int bn = blockIdx.x >> 2, colt = blockIdx.x & 3;
    int b = bn / 5;
    int q0 = colt * 49;
    int t = threadIdx.x;

    for (int i = t; i < 128*56; i += 224) {
        int c = i / 56, cp = i - c*56;
        int col = cp < 49 ? cp : 48;
        sm->Qt[cp][c] = g_qkv[b*OHW + c*HW + q0 + col];
    }

    int sg = t / 56, scp = t - sg*56;
    int r0 = sg * 7;
    int dg = t / 28, cp2 = t - dg*28;
    int dvb = dg * 16, c20 = cp2 * 2;

    float accv[16][2];
    #pragma unroll
    for (int i = 0; i < 16; i++) { accv[i][0] = 0.f; accv[i][1] = 0.f; }
    float ssum = 0.f;

    __syncthreads();

    for (int ch = 0; ch < 35; ch++) {
        int k = ch / 7, ij0 = (ch - k*7) * 28;
        const float* kb = g_skv + (bn*5 + k)*OHW + ij0;
        for (int i = t; i < 128*28; i += 224) {
            int c = i / 28, r = i - c*28;
            sm->Kr[r][c] = kb[c*HW + r];
        }
        for (int i = t; i < 128*28; i += 224) {
            int dv = i / 28, r = i - dv*28;
            sm->Vs[dv][r] = kb[(128 + dv)*HW + r];
        }
        __syncthreads();

        float sa[7];
        #pragma unroll
        for (int i = 0; i < 7; i++) sa[i] = 0.f;
        #pragma unroll 4
        for (int c4 = 0; c4 < 128; c4 += 4) {
            float4 q = *(const float4*)&sm->Qt[scp][c4];
            #pragma unroll
            for (int i = 0; i < 7; i++) {
                float4 kv = *(const float4*)&sm->Kr[r0 + i][c4];
                sa[i] = fmaf(kv.x, q.x, fmaf(kv.y, q.y, fmaf(kv.z, q.z, fmaf(kv.w, q.w, sa[i]))));
            }
        }
        #pragma unroll
        for (int i = 0; i < 7; i++) {
            float e = __expf(sa[i] * SCALE);
            sm->Et[scp][r0 + i] = e;
            ssum += e;
        }
        __syncthreads();

        #pragma unroll
        for (int r4 = 0; r4 < 28; r4 += 4) {
            float4 e0 = *(const float4*)&sm->Et[c20][r4];
            float4 e1 = *(const float4*)&sm->Et[c20 + 1][r4];
            #pragma unroll
            for (int i = 0; i < 16; i++) {
                float4 v = *(const float4*)&sm->Vs[dvb + i][r4];
                accv[i][0] = fmaf(v.x, e0.x, fmaf(v.y, e0.y, fmaf(v.z, e0.z, fmaf(v.w, e0.w, accv[i][0]))));
                accv[i][1] = fmaf(v.x, e1.x, fmaf(v.y, e1.y, fmaf(v.z, e1.z, fmaf(v.w, e1.w, accv[i][1]))));
            }
        }
        __syncthreads();
    }

    sm->Sred[sg][scp] = ssum;
    __syncthreads();

    float ss = 0.f;
    #pragma unroll
    for (int cc = 0; cc < 2; cc++) {
        int col = c20 + cc;
        if (col < 49) {
            float inv = 1.f / (sm->Sred[0][col] + sm->Sred[1][col] + sm->Sred[2][col] + sm->Sred[3][col]);
            int hw = q0 + col;
            #pragma unroll
            for (int i = 0; i < 16; i++) {
                int dv = dvb + i;
                float o = accv[i][cc] * inv;
                float w = g_wt[b*64*HW + (dv & 63)*HW + hw];
                float qv = g_qkv[b*OHW + (128 + dv)*HW + hw];
                float d = qv - o;
                ss = fmaf(w, d*d, ss);
            }
        }
    }
    #pragma unroll
    for (int o = 16; o > 0; o >>= 1) ss += __shfl_down_sync(0xFFFFFFFF, ss, o);
    if ((t & 31) == 0) sm->Rr[t >> 5] = ss;
    __syncthreads();
    if (t == 0) {
        float tot = 0.f;
        #pragma unroll
        for (int i = 0; i < 7; i++) tot += sm->Rr[i];
        g_part[bn*4 + colt] = tot;
    }
}

// ---------------- K6: deterministic final reduction ----------------
__global__ void k_fin(float* __restrict__ out) {
    int bn = threadIdx.x;
    if (bn < BN) {
        float* p = g_part + bn*4;
        out[bn] = -(p[0] + p[1] + p[2] + p[3]) * (1.f/HW);
    }
}

// ---------------- launch ----------------
extern "C" void kernel_launch(void* const* d_in, const int* in_sizes, int n_in,
                              void* d_out, int out_size) {
    const float* qry = (const float*)d_in[0];
    const float* sup = (const float*)d_in[1];
    const float* wqk = (const float*)d_in[2];
    const float* wv  = (const float*)d_in[3];
    const float* ws1 = (const float*)d_in[4];
    const float* ws2 = (const float*)d_in[5];
    float* out = (float*)d_out;

    cudaFuncSetAttribute(k_att, cudaFuncAttributeMaxDynamicSharedMemorySize, (int)sizeof(AttSmem));

    k_cvt_w<<<256, 128>>>(wqk, wv);
    k_cvt_x<<<SQ*7, 256>>>(sup, qry);
    k_avg<<<C, 256>>>(sup);
    k_t1<<<B, 224>>>(qry, ws1);
    k_mma<<<832, 256>>>(0);
    k_bias2<<<1, 64>>>(ws1);
    k_wt<<<32, 196>>>(ws2);
    k_att<<<160, 224, sizeof(AttSmem)>>>();
    k_fin<<<1, 64>>>(out);
}